// round 6
// baseline (speedup 1.0000x reference)
#include <cuda_runtime.h>
#include <cuda_bf16.h>

#define NN 50000
#define EE 600000
#define DD 128
#define LL 4
#define GG 128

// ---------------- scratch (device globals; referenced ONLY in device code) ----------------
static __device__ int   g_degi[NN];
static __device__ float g_dinv[NN];
static __device__ int   g_off[NN + 1];
static __device__ int   g_cursor[NN];
static __device__ int   g_bsum[64];
static __device__ int   g_esrc[EE];
static __device__ float g_ecoef[EE];
static __device__ float g_xc[NN * DD];   // current features (in-place per layer)
static __device__ float g_h[NN * DD];    // x @ W
static __device__ float g_sums[GG * DD];
static __device__ float g_cnt[GG];

// ---------------- init + copy fused ----------------
__global__ void k_initcopy(const float* __restrict__ x) {
    int i = blockIdx.x * blockDim.x + threadIdx.x;
    if (i < NN * DD / 4)
        ((float4*)g_xc)[i] = ((const float4*)x)[i];
    if (i < NN) { g_degi[i] = 0; g_cursor[i] = 0; }
    if (i < GG * DD) g_sums[i] = 0.f;
    if (i < GG) g_cnt[i] = 0.f;
}

// ---------------- degree histogram (by dst) ----------------
__global__ void k_deg(const int* __restrict__ dst) {
    int e = blockIdx.x * blockDim.x + threadIdx.x;
    if (e < EE) atomicAdd(&g_degi[dst[e]], 1);
}

// ---------------- graph-size histogram: block-local then global ----------------
__global__ void k_cnt(const int* __restrict__ batch) {
    __shared__ int hist[GG];
    int tid = threadIdx.x;
    if (tid < GG) hist[tid] = 0;
    __syncthreads();
    int n = blockIdx.x * blockDim.x + tid;
    if (n < NN) atomicAdd(&hist[batch[n]], 1);
    __syncthreads();
    if (tid < GG && hist[tid] > 0) atomicAdd(&g_cnt[tid], (float)hist[tid]);
}

__global__ void k_dinv() {
    int n = blockIdx.x * blockDim.x + threadIdx.x;
    if (n < NN) g_dinv[n] = rsqrtf((float)g_degi[n] + 1.0f);
}

// ---------------- exclusive scan of g_degi -> g_off ----------------
#define SCB 1024
__global__ void k_scan1() {
    __shared__ int sh[SCB];
    int i = blockIdx.x * SCB + threadIdx.x;
    int v = (i < NN) ? g_degi[i] : 0;
    sh[threadIdx.x] = v;
    __syncthreads();
#pragma unroll
    for (int o = 1; o < SCB; o <<= 1) {
        int t = 0;
        if ((int)threadIdx.x >= o) t = sh[threadIdx.x - o];
        __syncthreads();
        if ((int)threadIdx.x >= o) sh[threadIdx.x] += t;
        __syncthreads();
    }
    if (i < NN) g_off[i] = sh[threadIdx.x] - v;
    if (threadIdx.x == SCB - 1) g_bsum[blockIdx.x] = sh[SCB - 1];
}

__global__ void k_scan2(int nblocks) {
    if (threadIdx.x == 0) {
        int run = 0;
        for (int b = 0; b < nblocks; b++) {
            int t = g_bsum[b];
            g_bsum[b] = run;
            run += t;
        }
    }
}

__global__ void k_scan3() {
    int i = blockIdx.x * SCB + threadIdx.x;
    if (i < NN) g_off[i] += g_bsum[blockIdx.x];
    if (i == NN) g_off[NN] = EE;
}

// ---------------- fill CSR ----------------
__global__ void k_fill(const int* __restrict__ src, const int* __restrict__ dst) {
    int e = blockIdx.x * blockDim.x + threadIdx.x;
    if (e >= EE) return;
    int s = src[e], d = dst[e];
    int p = g_off[d] + atomicAdd(&g_cursor[d], 1);
    g_esrc[p] = s;
    g_ecoef[p] = g_dinv[s] * g_dinv[d];
}

// ---------------- tensor-core GEMM: g_h = g_xc @ W[l], 3xTF32 ----------------
__device__ __forceinline__ unsigned f2tf(float f) {
    unsigned r;
    asm("cvt.rna.tf32.f32 %0, %1;" : "=r"(r) : "f"(f));
    return r;
}

#define MMA_TF32(c, a0, a1, a2, a3, b0, b1)                                  \
    asm volatile(                                                            \
        "mma.sync.aligned.m16n8k8.row.col.f32.tf32.tf32.f32 "                \
        "{%0,%1,%2,%3}, {%4,%5,%6,%7}, {%8,%9}, {%0,%1,%2,%3};"              \
        : "+f"(c[0]), "+f"(c[1]), "+f"(c[2]), "+f"(c[3])                     \
        : "r"(a0), "r"(a1), "r"(a2), "r"(a3), "r"(b0), "r"(b1))

#define WSS 132  // padded stride (floats) -> conflict-free B fragment loads

__global__ void __launch_bounds__(256) k_gemm_tc(const float* __restrict__ Wl) {
    __shared__ unsigned Ws_hi[32 * WSS];
    __shared__ unsigned Ws_lo[32 * WSS];
    int tid = threadIdx.x;
    int warp = tid >> 5, lane = tid & 31;
    int gID = lane >> 2, tig = lane & 3;
    int rA = blockIdx.x * 128 + warp * 16 + gID;
    int rB = rA + 8;
    bool vA = rA < NN, vB = rB < NN;

    float acc[16][4];
#pragma unroll
    for (int i = 0; i < 16; i++) {
        acc[i][0] = 0.f; acc[i][1] = 0.f; acc[i][2] = 0.f; acc[i][3] = 0.f;
    }

    for (int kt = 0; kt < DD; kt += 32) {
        __syncthreads();  // protect Ws from previous tile's consumers
#pragma unroll
        for (int i = 0; i < 16; i++) {
            int idx = tid + i * 256;
            int kk = idx >> 7, n = idx & 127;
            float w = Wl[(kt + kk) * DD + n];
            unsigned whi = f2tf(w);
            Ws_hi[kk * WSS + n] = whi;
            Ws_lo[kk * WSS + n] = f2tf(w - __uint_as_float(whi));
        }
        __syncthreads();
#pragma unroll
        for (int ks = 0; ks < 32; ks += 8) {
            int k0 = kt + ks;
            float a0f = vA ? g_xc[rA * DD + k0 + tig] : 0.f;
            float a2f = vA ? g_xc[rA * DD + k0 + tig + 4] : 0.f;
            float a1f = vB ? g_xc[rB * DD + k0 + tig] : 0.f;
            float a3f = vB ? g_xc[rB * DD + k0 + tig + 4] : 0.f;
            unsigned ah0 = f2tf(a0f), ah1 = f2tf(a1f), ah2 = f2tf(a2f), ah3 = f2tf(a3f);
            unsigned al0 = f2tf(a0f - __uint_as_float(ah0));
            unsigned al1 = f2tf(a1f - __uint_as_float(ah1));
            unsigned al2 = f2tf(a2f - __uint_as_float(ah2));
            unsigned al3 = f2tf(a3f - __uint_as_float(ah3));
#pragma unroll
            for (int nt = 0; nt < 16; nt++) {
                int bb = (ks + tig) * WSS + nt * 8 + gID;
                unsigned b0h = Ws_hi[bb], b1h = Ws_hi[bb + 4 * WSS];
                unsigned b0l = Ws_lo[bb], b1l = Ws_lo[bb + 4 * WSS];
                MMA_TF32(acc[nt], ah0, ah1, ah2, ah3, b0h, b1h);
                MMA_TF32(acc[nt], ah0, ah1, ah2, ah3, b0l, b1l);
                MMA_TF32(acc[nt], al0, al1, al2, al3, b0h, b1h);
            }
        }
    }
#pragma unroll
    for (int nt = 0; nt < 16; nt++) {
        int c = nt * 8 + tig * 2;
        if (vA) *(float2*)&g_h[rA * DD + c] = make_float2(acc[nt][0], acc[nt][1]);
        if (vB) *(float2*)&g_h[rB * DD + c] = make_float2(acc[nt][2], acc[nt][3]);
    }
}

// ---------------- fused: gather-agg + self-loop + residual + bias + LN + ReLU ----------------
__global__ void k_agg(const float* __restrict__ bl,
                      const float* __restrict__ gl,
                      const float* __restrict__ betal) {
    int warp = (blockIdx.x * blockDim.x + threadIdx.x) >> 5;
    if (warp >= NN) return;
    int lane = threadIdx.x & 31;
    int n = warp;
    int c4 = lane * 4;

    float4 acc = make_float4(0.f, 0.f, 0.f, 0.f);
    int j = g_off[n];
    int jend = g_off[n + 1];
    for (; j + 3 < jend; j += 4) {
        int s0 = g_esrc[j],     s1 = g_esrc[j + 1];
        int s2 = g_esrc[j + 2], s3 = g_esrc[j + 3];
        float c0 = g_ecoef[j],     c1 = g_ecoef[j + 1];
        float c2 = g_ecoef[j + 2], c3 = g_ecoef[j + 3];
        float4 h0 = *(const float4*)&g_h[s0 * DD + c4];
        float4 h1 = *(const float4*)&g_h[s1 * DD + c4];
        float4 h2 = *(const float4*)&g_h[s2 * DD + c4];
        float4 h3 = *(const float4*)&g_h[s3 * DD + c4];
        acc.x += h0.x * c0 + h1.x * c1 + h2.x * c2 + h3.x * c3;
        acc.y += h0.y * c0 + h1.y * c1 + h2.y * c2 + h3.y * c3;
        acc.z += h0.z * c0 + h1.z * c1 + h2.z * c2 + h3.z * c3;
        acc.w += h0.w * c0 + h1.w * c1 + h2.w * c2 + h3.w * c3;
    }
    for (; j < jend; j++) {
        int s0 = g_esrc[j];
        float c0 = g_ecoef[j];
        float4 h0 = *(const float4*)&g_h[s0 * DD + c4];
        acc.x += h0.x * c0;
        acc.y += h0.y * c0;
        acc.z += h0.z * c0;
        acc.w += h0.w * c0;
    }

    float di = g_dinv[n];
    float self = di * di;
    int base = n * DD + c4;
    float4 xv = *(const float4*)&g_xc[base];
    float4 hv = *(const float4*)&g_h[base];
    float4 bv = *(const float4*)&bl[c4];

    float v0 = xv.x + acc.x + hv.x * self + bv.x;
    float v1 = xv.y + acc.y + hv.y * self + bv.y;
    float v2 = xv.z + acc.z + hv.z * self + bv.z;
    float v3 = xv.w + acc.w + hv.w * self + bv.w;

    float s = v0 + v1 + v2 + v3;
#pragma unroll
    for (int o = 16; o > 0; o >>= 1) s += __shfl_xor_sync(0xffffffffu, s, o);
    float m = s * (1.0f / DD);

    float d0 = v0 - m, d1 = v1 - m, d2 = v2 - m, d3 = v3 - m;
    float sq = d0 * d0 + d1 * d1 + d2 * d2 + d3 * d3;
#pragma unroll
    for (int o = 16; o > 0; o >>= 1) sq += __shfl_xor_sync(0xffffffffu, sq, o);
    float inv = rsqrtf(sq * (1.0f / DD) + 1e-5f);

    float4 gv = *(const float4*)&gl[c4];
    float4 tv = *(const float4*)&betal[c4];
    float4 outv;
    outv.x = fmaxf(d0 * inv * gv.x + tv.x, 0.f);
    outv.y = fmaxf(d1 * inv * gv.y + tv.y, 0.f);
    outv.z = fmaxf(d2 * inv * gv.z + tv.z, 0.f);
    outv.w = fmaxf(d3 * inv * gv.w + tv.w, 0.f);
    *(float4*)&g_xc[base] = outv;
}

// ---------------- global mean pool: warp-chunked accumulation ----------------
#define CH 16
__global__ void k_pool(const int* __restrict__ batch) {
    int warp = (blockIdx.x * blockDim.x + threadIdx.x) >> 5;
    int lane = threadIdx.x & 31;
    int n0 = warp * CH;
    if (n0 >= NN) return;
    int n1 = n0 + CH;
    if (n1 > NN) n1 = NN;

    float4 acc = make_float4(0.f, 0.f, 0.f, 0.f);
    int cur = batch[n0];
    for (int n = n0; n < n1; n++) {
        int g = batch[n];
        if (g != cur) {
            float* sp = &g_sums[cur * DD + lane * 4];
            atomicAdd(sp + 0, acc.x);
            atomicAdd(sp + 1, acc.y);
            atomicAdd(sp + 2, acc.z);
            atomicAdd(sp + 3, acc.w);
            acc = make_float4(0.f, 0.f, 0.f, 0.f);
            cur = g;
        }
        float4 xv = *(const float4*)&g_xc[n * DD + lane * 4];
        acc.x += xv.x; acc.y += xv.y; acc.z += xv.z; acc.w += xv.w;
    }
    float* sp = &g_sums[cur * DD + lane * 4];
    atomicAdd(sp + 0, acc.x);
    atomicAdd(sp + 1, acc.y);
    atomicAdd(sp + 2, acc.z);
    atomicAdd(sp + 3, acc.w);
}

__global__ void k_out(float* __restrict__ out) {
    int i = blockIdx.x * blockDim.x + threadIdx.x;
    if (i < GG * DD) out[i] = g_sums[i] / fmaxf(g_cnt[i >> 7], 1.0f);
}

// ---------------- launch (host passes ONLY harness pointers) ----------------
extern "C" void kernel_launch(void* const* d_in, const int* in_sizes, int n_in,
                              void* d_out, int out_size) {
    const float* x = (const float*)d_in[0];
    const int* ei = (const int*)d_in[1];
    const int* batch = (const int*)d_in[2];
    const float* W = (const float*)d_in[3];
    const float* b = (const float*)d_in[4];
    const float* gamma = (const float*)d_in[5];
    const float* beta = (const float*)d_in[6];
    float* out = (float*)d_out;

    const int* src = ei;
    const int* dst = ei + EE;

    int nscan = (NN + SCB - 1) / SCB;  // 49

    k_initcopy<<<(NN * DD / 4 + 255) / 256, 256>>>(x);
    k_deg<<<(EE + 255) / 256, 256>>>(dst);
    k_cnt<<<(NN + 255) / 256, 256>>>(batch);
    k_dinv<<<(NN + 255) / 256, 256>>>();
    k_scan1<<<nscan, SCB>>>();
    k_scan2<<<1, 32>>>(nscan);
    k_scan3<<<nscan + 1, SCB>>>();
    k_fill<<<(EE + 255) / 256, 256>>>(src, dst);

    for (int l = 0; l < LL; l++) {
        k_gemm_tc<<<(NN + 127) / 128, 256>>>(W + l * DD * DD);
        k_agg<<<(NN * 32 + 255) / 256, 256>>>(b + l * DD, gamma + l * DD, beta + l * DD);
    }

    k_pool<<<((NN + CH - 1) / CH * 32 + 255) / 256, 256>>>(batch);
    k_out<<<(GG * DD + 255) / 256, 256>>>(out);
}

// round 8
// speedup vs baseline: 1.4698x; 1.4698x over previous
#include <cuda_runtime.h>
#include <cuda_bf16.h>

#define NN 50000
#define EE 600000
#define DD 128
#define LL 4
#define GG 128

// ---------------- scratch (device globals; referenced ONLY in device code) ----------------
static __device__ int   g_degi[NN];
static __device__ float g_dinv[NN];
static __device__ int   g_off[NN + 1];
static __device__ int   g_cursor[NN];
static __device__ int   g_bsum[64];
static __device__ int   g_esrc[EE];
static __device__ float g_ecoef[EE];
static __device__ float g_xc[NN * DD];       // current features (in-place per layer)
static __device__ float g_h[NN * DD];        // x @ W
static __device__ uint4 g_wsplit[LL * 4096]; // pre-split bf16 W in fragment layout
static __device__ float g_sums[GG * DD];
static __device__ float g_cnt[GG];

// ---------------- init + copy fused ----------------
__global__ void k_initcopy(const float* __restrict__ x) {
    int i = blockIdx.x * blockDim.x + threadIdx.x;
    if (i < NN * DD / 4)
        ((float4*)g_xc)[i] = ((const float4*)x)[i];
    if (i < NN) { g_degi[i] = 0; g_cursor[i] = 0; }
    if (i < GG * DD) g_sums[i] = 0.f;
    if (i < GG) g_cnt[i] = 0.f;
}

// ---------------- degree histogram (by dst) ----------------
__global__ void k_deg(const int* __restrict__ dst) {
    int e = blockIdx.x * blockDim.x + threadIdx.x;
    if (e < EE) atomicAdd(&g_degi[dst[e]], 1);
}

// ---------------- graph-size histogram: block-local then global ----------------
__global__ void k_cnt(const int* __restrict__ batch) {
    __shared__ int hist[GG];
    int tid = threadIdx.x;
    if (tid < GG) hist[tid] = 0;
    __syncthreads();
    int n = blockIdx.x * blockDim.x + tid;
    if (n < NN) atomicAdd(&hist[batch[n]], 1);
    __syncthreads();
    if (tid < GG && hist[tid] > 0) atomicAdd(&g_cnt[tid], (float)hist[tid]);
}

// ---------------- split W into bf16 hi/lo, pre-swizzled fragment layout ----------------
__device__ __forceinline__ unsigned pack_bf(float lo_f, float hi_f) {
    __nv_bfloat162 p;
    p.x = __float2bfloat16(lo_f);   // .x = low half (even k)
    p.y = __float2bfloat16(hi_f);
    return *(unsigned*)&p;
}

__global__ void k_wsplit(const float* __restrict__ W) {
    int t = blockIdx.x * blockDim.x + threadIdx.x;
    if (t >= LL * 4096) return;
    int l = t >> 12;
    int u = t & 4095;
    int tig = u & 3;
    int nlow = (u >> 2) & 1;
    int kc = (u >> 3) & 7;
    int npair = u >> 6;
    int n = npair * 2 + nlow;
    int k0 = kc * 16 + tig * 2;
    const float* Wl = W + l * DD * DD;
    float w00 = Wl[k0 * DD + n],       w01 = Wl[(k0 + 1) * DD + n];
    float w80 = Wl[(k0 + 8) * DD + n], w81 = Wl[(k0 + 9) * DD + n];
    float h00 = __bfloat162float(__float2bfloat16(w00));
    float h01 = __bfloat162float(__float2bfloat16(w01));
    float h80 = __bfloat162float(__float2bfloat16(w80));
    float h81 = __bfloat162float(__float2bfloat16(w81));
    uint4 v;
    v.x = pack_bf(w00, w01);             // b0 hi
    v.y = pack_bf(w80, w81);             // b1 hi
    v.z = pack_bf(w00 - h00, w01 - h01); // b0 lo
    v.w = pack_bf(w80 - h80, w81 - h81); // b1 lo
    g_wsplit[t] = v;
}

// ---------------- exclusive scan of g_degi -> g_off (also computes dinv) ----------------
#define SCB 1024
__global__ void k_scan1() {
    __shared__ int sh[SCB];
    int i = blockIdx.x * SCB + threadIdx.x;
    int v = (i < NN) ? g_degi[i] : 0;
    if (i < NN) g_dinv[i] = rsqrtf((float)v + 1.0f);
    sh[threadIdx.x] = v;
    __syncthreads();
#pragma unroll
    for (int o = 1; o < SCB; o <<= 1) {
        int t = 0;
        if ((int)threadIdx.x >= o) t = sh[threadIdx.x - o];
        __syncthreads();
        if ((int)threadIdx.x >= o) sh[threadIdx.x] += t;
        __syncthreads();
    }
    if (i < NN) g_off[i] = sh[threadIdx.x] - v;
    if (threadIdx.x == SCB - 1) g_bsum[blockIdx.x] = sh[SCB - 1];
}

__global__ void k_scan2(int nblocks) {
    if (threadIdx.x == 0) {
        int run = 0;
        for (int b = 0; b < nblocks; b++) {
            int t = g_bsum[b];
            g_bsum[b] = run;
            run += t;
        }
    }
}

__global__ void k_scan3() {
    int i = blockIdx.x * SCB + threadIdx.x;
    if (i < NN) g_off[i] += g_bsum[blockIdx.x];
    if (i == NN) g_off[NN] = EE;
}

// ---------------- fill CSR ----------------
__global__ void k_fill(const int* __restrict__ src, const int* __restrict__ dst) {
    int e = blockIdx.x * blockDim.x + threadIdx.x;
    if (e >= EE) return;
    int s = src[e], d = dst[e];
    int p = g_off[d] + atomicAdd(&g_cursor[d], 1);
    g_esrc[p] = s;
    g_ecoef[p] = g_dinv[s] * g_dinv[d];
}

// ---------------- tensor-core GEMM: g_h = g_xc @ W[l], bf16 split (hi+lo) ----------------
#define MMA_BF16(c, a0, a1, a2, a3, b0, b1)                                  \
    asm volatile(                                                            \
        "mma.sync.aligned.m16n8k16.row.col.f32.bf16.bf16.f32 "               \
        "{%0,%1,%2,%3}, {%4,%5,%6,%7}, {%8,%9}, {%0,%1,%2,%3};"              \
        : "+f"(c[0]), "+f"(c[1]), "+f"(c[2]), "+f"(c[3])                     \
        : "r"(a0), "r"(a1), "r"(a2), "r"(a3), "r"(b0), "r"(b1))

__device__ __forceinline__ void split2(float2 f, unsigned& hi, unsigned& lo) {
    float hx = __bfloat162float(__float2bfloat16(f.x));
    float hy = __bfloat162float(__float2bfloat16(f.y));
    hi = pack_bf(f.x, f.y);
    lo = pack_bf(f.x - hx, f.y - hy);
}

__global__ void __launch_bounds__(256) k_gemm_bf16(int l) {
    extern __shared__ uint4 Bs[];  // 4096 uint4 = 64KB, fragment layout
    int tid = threadIdx.x;
    const uint4* wsrc = g_wsplit + l * 4096;
#pragma unroll
    for (int i = 0; i < 16; i++) Bs[tid + i * 256] = wsrc[tid + i * 256];
    __syncthreads();

    int warp = tid >> 5, lane = tid & 31;
    int gID = lane >> 2, tig = lane & 3;
    int rA = blockIdx.x * 128 + warp * 16 + gID;
    int rB = rA + 8;
    bool vA = rA < NN, vB = rB < NN;
    int tb = (gID >> 1) * 64 + (gID & 1) * 4 + tig;  // per-thread smem base

    float acc[16][4];
#pragma unroll
    for (int i = 0; i < 16; i++) {
        acc[i][0] = 0.f; acc[i][1] = 0.f; acc[i][2] = 0.f; acc[i][3] = 0.f;
    }

    const float2 z2 = make_float2(0.f, 0.f);
#pragma unroll
    for (int kc = 0; kc < 8; kc++) {
        int kb = kc * 16 + tig * 2;
        float2 fA0 = vA ? *(const float2*)&g_xc[rA * DD + kb] : z2;
        float2 fA8 = vA ? *(const float2*)&g_xc[rA * DD + kb + 8] : z2;
        float2 fB0 = vB ? *(const float2*)&g_xc[rB * DD + kb] : z2;
        float2 fB8 = vB ? *(const float2*)&g_xc[rB * DD + kb + 8] : z2;
        unsigned ah0, al0, ah1, al1, ah2, al2, ah3, al3;
        split2(fA0, ah0, al0);  // a0: row rA,  k lo
        split2(fB0, ah1, al1);  // a1: row rB,  k lo
        split2(fA8, ah2, al2);  // a2: row rA,  k hi
        split2(fB8, ah3, al3);  // a3: row rB,  k hi
#pragma unroll
        for (int nt = 0; nt < 16; nt++) {
            uint4 bv = Bs[nt * 256 + kc * 8 + tb];
            MMA_BF16(acc[nt], ah0, ah1, ah2, ah3, bv.x, bv.y);  // hi*hi
            MMA_BF16(acc[nt], ah0, ah1, ah2, ah3, bv.z, bv.w);  // hi*lo
            MMA_BF16(acc[nt], al0, al1, al2, al3, bv.x, bv.y);  // lo*hi
        }
    }
#pragma unroll
    for (int nt = 0; nt < 16; nt++) {
        int c = nt * 8 + tig * 2;
        if (vA) *(float2*)&g_h[rA * DD + c] = make_float2(acc[nt][0], acc[nt][1]);
        if (vB) *(float2*)&g_h[rB * DD + c] = make_float2(acc[nt][2], acc[nt][3]);
    }
}

// ---------------- fused: gather-agg + self-loop + residual + bias + LN + ReLU ----------------
__global__ void k_agg(const float* __restrict__ bl,
                      const float* __restrict__ gl,
                      const float* __restrict__ betal) {
    int warp = (blockIdx.x * blockDim.x + threadIdx.x) >> 5;
    if (warp >= NN) return;
    int lane = threadIdx.x & 31;
    int n = warp;
    int c4 = lane * 4;

    float4 acc = make_float4(0.f, 0.f, 0.f, 0.f);
    int j = g_off[n];
    int jend = g_off[n + 1];
    for (; j + 3 < jend; j += 4) {
        int s0 = g_esrc[j],     s1 = g_esrc[j + 1];
        int s2 = g_esrc[j + 2], s3 = g_esrc[j + 3];
        float c0 = g_ecoef[j],     c1 = g_ecoef[j + 1];
        float c2 = g_ecoef[j + 2], c3 = g_ecoef[j + 3];
        float4 h0 = *(const float4*)&g_h[s0 * DD + c4];
        float4 h1 = *(const float4*)&g_h[s1 * DD + c4];
        float4 h2 = *(const float4*)&g_h[s2 * DD + c4];
        float4 h3 = *(const float4*)&g_h[s3 * DD + c4];
        acc.x += h0.x * c0 + h1.x * c1 + h2.x * c2 + h3.x * c3;
        acc.y += h0.y * c0 + h1.y * c1 + h2.y * c2 + h3.y * c3;
        acc.z += h0.z * c0 + h1.z * c1 + h2.z * c2 + h3.z * c3;
        acc.w += h0.w * c0 + h1.w * c1 + h2.w * c2 + h3.w * c3;
    }
    for (; j < jend; j++) {
        int s0 = g_esrc[j];
        float c0 = g_ecoef[j];
        float4 h0 = *(const float4*)&g_h[s0 * DD + c4];
        acc.x += h0.x * c0;
        acc.y += h0.y * c0;
        acc.z += h0.z * c0;
        acc.w += h0.w * c0;
    }

    float di = g_dinv[n];
    float self = di * di;
    int base = n * DD + c4;
    float4 xv = *(const float4*)&g_xc[base];
    float4 hv = *(const float4*)&g_h[base];
    float4 bv = *(const float4*)&bl[c4];

    float v0 = xv.x + acc.x + hv.x * self + bv.x;
    float v1 = xv.y + acc.y + hv.y * self + bv.y;
    float v2 = xv.z + acc.z + hv.z * self + bv.z;
    float v3 = xv.w + acc.w + hv.w * self + bv.w;

    float s = v0 + v1 + v2 + v3;
#pragma unroll
    for (int o = 16; o > 0; o >>= 1) s += __shfl_xor_sync(0xffffffffu, s, o);
    float m = s * (1.0f / DD);

    float d0 = v0 - m, d1 = v1 - m, d2 = v2 - m, d3 = v3 - m;
    float sq = d0 * d0 + d1 * d1 + d2 * d2 + d3 * d3;
#pragma unroll
    for (int o = 16; o > 0; o >>= 1) sq += __shfl_xor_sync(0xffffffffu, sq, o);
    float inv = rsqrtf(sq * (1.0f / DD) + 1e-5f);

    float4 gv = *(const float4*)&gl[c4];
    float4 tv = *(const float4*)&betal[c4];
    float4 outv;
    outv.x = fmaxf(d0 * inv * gv.x + tv.x, 0.f);
    outv.y = fmaxf(d1 * inv * gv.y + tv.y, 0.f);
    outv.z = fmaxf(d2 * inv * gv.z + tv.z, 0.f);
    outv.w = fmaxf(d3 * inv * gv.w + tv.w, 0.f);
    *(float4*)&g_xc[base] = outv;
}

// ---------------- global mean pool: warp-chunked accumulation ----------------
#define CH 16
__global__ void k_pool(const int* __restrict__ batch) {
    int warp = (blockIdx.x * blockDim.x + threadIdx.x) >> 5;
    int lane = threadIdx.x & 31;
    int n0 = warp * CH;
    if (n0 >= NN) return;
    int n1 = n0 + CH;
    if (n1 > NN) n1 = NN;

    float4 acc = make_float4(0.f, 0.f, 0.f, 0.f);
    int cur = batch[n0];
    for (int n = n0; n < n1; n++) {
        int g = batch[n];
        if (g != cur) {
            float* sp = &g_sums[cur * DD + lane * 4];
            atomicAdd(sp + 0, acc.x);
            atomicAdd(sp + 1, acc.y);
            atomicAdd(sp + 2, acc.z);
            atomicAdd(sp + 3, acc.w);
            acc = make_float4(0.f, 0.f, 0.f, 0.f);
            cur = g;
        }
        float4 xv = *(const float4*)&g_xc[n * DD + lane * 4];
        acc.x += xv.x; acc.y += xv.y; acc.z += xv.z; acc.w += xv.w;
    }
    float* sp = &g_sums[cur * DD + lane * 4];
    atomicAdd(sp + 0, acc.x);
    atomicAdd(sp + 1, acc.y);
    atomicAdd(sp + 2, acc.z);
    atomicAdd(sp + 3, acc.w);
}

__global__ void k_out(float* __restrict__ out) {
    int i = blockIdx.x * blockDim.x + threadIdx.x;
    if (i < GG * DD) out[i] = g_sums[i] / fmaxf(g_cnt[i >> 7], 1.0f);
}

// ---------------- launch (host passes ONLY harness pointers) ----------------
extern "C" void kernel_launch(void* const* d_in, const int* in_sizes, int n_in,
                              void* d_out, int out_size) {
    const float* x = (const float*)d_in[0];
    const int* ei = (const int*)d_in[1];
    const int* batch = (const int*)d_in[2];
    const float* W = (const float*)d_in[3];
    const float* b = (const float*)d_in[4];
    const float* gamma = (const float*)d_in[5];
    const float* beta = (const float*)d_in[6];
    float* out = (float*)d_out;

    const int* src = ei;
    const int* dst = ei + EE;

    int nscan = (NN + SCB - 1) / SCB;  // 49

    cudaFuncSetAttribute(k_gemm_bf16, cudaFuncAttributeMaxDynamicSharedMemorySize, 65536);

    k_initcopy<<<(NN * DD / 4 + 255) / 256, 256>>>(x);
    k_deg<<<(EE + 255) / 256, 256>>>(dst);
    k_cnt<<<(NN + 255) / 256, 256>>>(batch);
    k_wsplit<<<(LL * 4096 + 255) / 256, 256>>>(W);
    k_scan1<<<nscan, SCB>>>();
    k_scan2<<<1, 32>>>(nscan);
    k_scan3<<<nscan + 1, SCB>>>();
    k_fill<<<(EE + 255) / 256, 256>>>(src, dst);

    for (int l = 0; l < LL; l++) {
        k_gemm_bf16<<<(NN + 127) / 128, 256, 65536>>>(l);
        k_agg<<<(NN * 32 + 255) / 256, 256>>>(b + l * DD, gamma + l * DD, beta + l * DD);
    }

    k_pool<<<((NN + CH - 1) / CH * 32 + 255) / 256, 256>>>(batch);
    k_out<<<(GG * DD + 255) / 256, 256>>>(out);
}

// round 10
// speedup vs baseline: 1.6498x; 1.1224x over previous
#include <cuda_runtime.h>
#include <cuda_bf16.h>
#include <cuda_fp16.h>

#define NN 50000
#define EE 600000
#define DD 128
#define LL 4
#define GG 128

// ---------------- scratch (device globals; referenced ONLY in device code) ----------------
static __device__ int    g_degi[NN];
static __device__ float  g_dinv[NN];
static __device__ int    g_off[NN + 1];
static __device__ int    g_cursor[NN];
static __device__ int    g_bsum[64];
static __device__ int    g_esrc[EE];
static __device__ float  g_ecoef[EE];
static __device__ float  g_xc[NN * DD];       // current features (in-place per layer)
static __device__ __half g_h16[NN * DD];      // x @ W in fp16 (gather payload)
static __device__ uint4  g_wsplit[LL * 4096]; // pre-split bf16 W in fragment layout
static __device__ float  g_sums[GG * DD];
static __device__ float  g_cnt[GG];

// ---------------- init + copy fused ----------------
__global__ void k_initcopy(const float* __restrict__ x) {
    int i = blockIdx.x * blockDim.x + threadIdx.x;
    if (i < NN * DD / 4)
        ((float4*)g_xc)[i] = ((const float4*)x)[i];
    if (i < NN) { g_degi[i] = 0; g_cursor[i] = 0; }
    if (i < GG * DD) g_sums[i] = 0.f;
    if (i < GG) g_cnt[i] = 0.f;
}

// ---------------- degree histogram (by dst) ----------------
__global__ void k_deg(const int* __restrict__ dst) {
    int e = blockIdx.x * blockDim.x + threadIdx.x;
    if (e < EE) atomicAdd(&g_degi[dst[e]], 1);
}

// ---------------- graph-size histogram: block-local then global ----------------
__global__ void k_cnt(const int* __restrict__ batch) {
    __shared__ int hist[GG];
    int tid = threadIdx.x;
    if (tid < GG) hist[tid] = 0;
    __syncthreads();
    int n = blockIdx.x * blockDim.x + tid;
    if (n < NN) atomicAdd(&hist[batch[n]], 1);
    __syncthreads();
    if (tid < GG && hist[tid] > 0) atomicAdd(&g_cnt[tid], (float)hist[tid]);
}

// ---------------- split W into bf16 hi/lo, pre-swizzled fragment layout ----------------
__device__ __forceinline__ unsigned pack_bf(float lo_f, float hi_f) {
    __nv_bfloat162 p;
    p.x = __float2bfloat16(lo_f);   // .x = low half (even k)
    p.y = __float2bfloat16(hi_f);
    return *(unsigned*)&p;
}

__global__ void k_wsplit(const float* __restrict__ W) {
    int t = blockIdx.x * blockDim.x + threadIdx.x;
    if (t >= LL * 4096) return;
    int l = t >> 12;
    int u = t & 4095;
    int tig = u & 3;
    int nlow = (u >> 2) & 1;
    int kc = (u >> 3) & 7;
    int npair = u >> 6;
    int n = npair * 2 + nlow;
    int k0 = kc * 16 + tig * 2;
    const float* Wl = W + l * DD * DD;
    float w00 = Wl[k0 * DD + n],       w01 = Wl[(k0 + 1) * DD + n];
    float w80 = Wl[(k0 + 8) * DD + n], w81 = Wl[(k0 + 9) * DD + n];
    float h00 = __bfloat162float(__float2bfloat16(w00));
    float h01 = __bfloat162float(__float2bfloat16(w01));
    float h80 = __bfloat162float(__float2bfloat16(w80));
    float h81 = __bfloat162float(__float2bfloat16(w81));
    uint4 v;
    v.x = pack_bf(w00, w01);             // b0 hi
    v.y = pack_bf(w80, w81);             // b1 hi
    v.z = pack_bf(w00 - h00, w01 - h01); // b0 lo
    v.w = pack_bf(w80 - h80, w81 - h81); // b1 lo
    g_wsplit[t] = v;
}

// ---------------- exclusive scan of g_degi -> g_off (also computes dinv) ----------------
#define SCB 1024
__global__ void k_scan1() {
    __shared__ int sh[SCB];
    int i = blockIdx.x * SCB + threadIdx.x;
    int v = (i < NN) ? g_degi[i] : 0;
    if (i < NN) g_dinv[i] = rsqrtf((float)v + 1.0f);
    sh[threadIdx.x] = v;
    __syncthreads();
#pragma unroll
    for (int o = 1; o < SCB; o <<= 1) {
        int t = 0;
        if ((int)threadIdx.x >= o) t = sh[threadIdx.x - o];
        __syncthreads();
        if ((int)threadIdx.x >= o) sh[threadIdx.x] += t;
        __syncthreads();
    }
    if (i < NN) g_off[i] = sh[threadIdx.x] - v;
    if (threadIdx.x == SCB - 1) g_bsum[blockIdx.x] = sh[SCB - 1];
}

__global__ void k_scan2(int nblocks) {
    if (threadIdx.x == 0) {
        int run = 0;
        for (int b = 0; b < nblocks; b++) {
            int t = g_bsum[b];
            g_bsum[b] = run;
            run += t;
        }
    }
}

__global__ void k_scan3() {
    int i = blockIdx.x * SCB + threadIdx.x;
    if (i < NN) g_off[i] += g_bsum[blockIdx.x];
    if (i == NN) g_off[NN] = EE;
}

// ---------------- fill CSR ----------------
__global__ void k_fill(const int* __restrict__ src, const int* __restrict__ dst) {
    int e = blockIdx.x * blockDim.x + threadIdx.x;
    if (e >= EE) return;
    int s = src[e], d = dst[e];
    int p = g_off[d] + atomicAdd(&g_cursor[d], 1);
    g_esrc[p] = s;
    g_ecoef[p] = g_dinv[s] * g_dinv[d];
}

// ---------------- tensor-core GEMM: g_h16 = fp16(g_xc @ W[l]), bf16 split ----------------
#define MMA_BF16(c, a0, a1, a2, a3, b0, b1)                                  \
    asm volatile(                                                            \
        "mma.sync.aligned.m16n8k16.row.col.f32.bf16.bf16.f32 "               \
        "{%0,%1,%2,%3}, {%4,%5,%6,%7}, {%8,%9}, {%0,%1,%2,%3};"              \
        : "+f"(c[0]), "+f"(c[1]), "+f"(c[2]), "+f"(c[3])                     \
        : "r"(a0), "r"(a1), "r"(a2), "r"(a3), "r"(b0), "r"(b1))

__device__ __forceinline__ void split2(float2 f, unsigned& hi, unsigned& lo) {
    float hx = __bfloat162float(__float2bfloat16(f.x));
    float hy = __bfloat162float(__float2bfloat16(f.y));
    hi = pack_bf(f.x, f.y);
    lo = pack_bf(f.x - hx, f.y - hy);
}

__global__ void __launch_bounds__(256) k_gemm_bf16(int l) {
    extern __shared__ uint4 Bs[];  // 4096 uint4 = 64KB, fragment layout
    int tid = threadIdx.x;
    const uint4* wsrc = g_wsplit + l * 4096;
#pragma unroll
    for (int i = 0; i < 16; i++) Bs[tid + i * 256] = wsrc[tid + i * 256];
    __syncthreads();

    int warp = tid >> 5, lane = tid & 31;
    int gID = lane >> 2, tig = lane & 3;
    int rA = blockIdx.x * 128 + warp * 16 + gID;
    int rB = rA + 8;
    bool vA = rA < NN, vB = rB < NN;
    int tb = (gID >> 1) * 64 + (gID & 1) * 4 + tig;  // per-thread smem base

    float acc[16][4];
#pragma unroll
    for (int i = 0; i < 16; i++) {
        acc[i][0] = 0.f; acc[i][1] = 0.f; acc[i][2] = 0.f; acc[i][3] = 0.f;
    }

    const float2 z2 = make_float2(0.f, 0.f);
#pragma unroll
    for (int kc = 0; kc < 8; kc++) {
        int kb = kc * 16 + tig * 2;
        float2 fA0 = vA ? *(const float2*)&g_xc[rA * DD + kb] : z2;
        float2 fA8 = vA ? *(const float2*)&g_xc[rA * DD + kb + 8] : z2;
        float2 fB0 = vB ? *(const float2*)&g_xc[rB * DD + kb] : z2;
        float2 fB8 = vB ? *(const float2*)&g_xc[rB * DD + kb + 8] : z2;
        unsigned ah0, al0, ah1, al1, ah2, al2, ah3, al3;
        split2(fA0, ah0, al0);
        split2(fB0, ah1, al1);
        split2(fA8, ah2, al2);
        split2(fB8, ah3, al3);
#pragma unroll
        for (int nt = 0; nt < 16; nt++) {
            uint4 bv = Bs[nt * 256 + kc * 8 + tb];
            MMA_BF16(acc[nt], ah0, ah1, ah2, ah3, bv.x, bv.y);  // hi*hi
            MMA_BF16(acc[nt], ah0, ah1, ah2, ah3, bv.z, bv.w);  // hi*lo
            MMA_BF16(acc[nt], al0, al1, al2, al3, bv.x, bv.y);  // lo*hi
        }
    }
#pragma unroll
    for (int nt = 0; nt < 16; nt++) {
        int c = nt * 8 + tig * 2;
        if (vA) {
            __half2 p = __floats2half2_rn(acc[nt][0], acc[nt][1]);
            *(__half2*)&g_h16[rA * DD + c] = p;
        }
        if (vB) {
            __half2 p = __floats2half2_rn(acc[nt][2], acc[nt][3]);
            *(__half2*)&g_h16[rB * DD + c] = p;
        }
    }
}

// ---------------- fused: gather-agg + self-loop + residual + bias + LN + ReLU ----------------
__device__ __forceinline__ float4 ld_h4(int s, int c4) {
    uint2 raw = *(const uint2*)&g_h16[s * DD + c4];
    __half2 p0 = *(__half2*)&raw.x;
    __half2 p1 = *(__half2*)&raw.y;
    float2 f0 = __half22float2(p0);
    float2 f1 = __half22float2(p1);
    return make_float4(f0.x, f0.y, f1.x, f1.y);
}

__global__ void k_agg(const float* __restrict__ bl,
                      const float* __restrict__ gl,
                      const float* __restrict__ betal) {
    int warp = (blockIdx.x * blockDim.x + threadIdx.x) >> 5;
    if (warp >= NN) return;
    int lane = threadIdx.x & 31;
    int n = warp;
    int c4 = lane * 4;

    float4 acc = make_float4(0.f, 0.f, 0.f, 0.f);
    int j = g_off[n];
    int jend = g_off[n + 1];
    for (; j + 3 < jend; j += 4) {
        int s0 = g_esrc[j],     s1 = g_esrc[j + 1];
        int s2 = g_esrc[j + 2], s3 = g_esrc[j + 3];
        float c0 = g_ecoef[j],     c1 = g_ecoef[j + 1];
        float c2 = g_ecoef[j + 2], c3 = g_ecoef[j + 3];
        float4 h0 = ld_h4(s0, c4);
        float4 h1 = ld_h4(s1, c4);
        float4 h2 = ld_h4(s2, c4);
        float4 h3 = ld_h4(s3, c4);
        acc.x += h0.x * c0 + h1.x * c1 + h2.x * c2 + h3.x * c3;
        acc.y += h0.y * c0 + h1.y * c1 + h2.y * c2 + h3.y * c3;
        acc.z += h0.z * c0 + h1.z * c1 + h2.z * c2 + h3.z * c3;
        acc.w += h0.w * c0 + h1.w * c1 + h2.w * c2 + h3.w * c3;
    }
    for (; j < jend; j++) {
        int s0 = g_esrc[j];
        float c0 = g_ecoef[j];
        float4 h0 = ld_h4(s0, c4);
        acc.x += h0.x * c0;
        acc.y += h0.y * c0;
        acc.z += h0.z * c0;
        acc.w += h0.w * c0;
    }

    float di = g_dinv[n];
    float self = di * di;
    int base = n * DD + c4;
    float4 xv = *(const float4*)&g_xc[base];
    float4 hv = ld_h4(n, c4);
    float4 bv = *(const float4*)&bl[c4];

    float v0 = xv.x + acc.x + hv.x * self + bv.x;
    float v1 = xv.y + acc.y + hv.y * self + bv.y;
    float v2 = xv.z + acc.z + hv.z * self + bv.z;
    float v3 = xv.w + acc.w + hv.w * self + bv.w;

    float s = v0 + v1 + v2 + v3;
#pragma unroll
    for (int o = 16; o > 0; o >>= 1) s += __shfl_xor_sync(0xffffffffu, s, o);
    float m = s * (1.0f / DD);

    float d0 = v0 - m, d1 = v1 - m, d2 = v2 - m, d3 = v3 - m;
    float sq = d0 * d0 + d1 * d1 + d2 * d2 + d3 * d3;
#pragma unroll
    for (int o = 16; o > 0; o >>= 1) sq += __shfl_xor_sync(0xffffffffu, sq, o);
    float inv = rsqrtf(sq * (1.0f / DD) + 1e-5f);

    float4 gv = *(const float4*)&gl[c4];
    float4 tv = *(const float4*)&betal[c4];
    float4 outv;
    outv.x = fmaxf(d0 * inv * gv.x + tv.x, 0.f);
    outv.y = fmaxf(d1 * inv * gv.y + tv.y, 0.f);
    outv.z = fmaxf(d2 * inv * gv.z + tv.z, 0.f);
    outv.w = fmaxf(d3 * inv * gv.w + tv.w, 0.f);
    *(float4*)&g_xc[base] = outv;
}

// ---------------- global mean pool: warp-chunked accumulation ----------------
#define CH 16
__global__ void k_pool(const int* __restrict__ batch) {
    int warp = (blockIdx.x * blockDim.x + threadIdx.x) >> 5;
    int lane = threadIdx.x & 31;
    int n0 = warp * CH;
    if (n0 >= NN) return;
    int n1 = n0 + CH;
    if (n1 > NN) n1 = NN;

    float4 acc = make_float4(0.f, 0.f, 0.f, 0.f);
    int cur = batch[n0];
    for (int n = n0; n < n1; n++) {
        int g = batch[n];
        if (g != cur) {
            float* sp = &g_sums[cur * DD + lane * 4];
            atomicAdd(sp + 0, acc.x);
            atomicAdd(sp + 1, acc.y);
            atomicAdd(sp + 2, acc.z);
            atomicAdd(sp + 3, acc.w);
            acc = make_float4(0.f, 0.f, 0.f, 0.f);
            cur = g;
        }
        float4 xv = *(const float4*)&g_xc[n * DD + lane * 4];
        acc.x += xv.x; acc.y += xv.y; acc.z += xv.z; acc.w += xv.w;
    }
    float* sp = &g_sums[cur * DD + lane * 4];
    atomicAdd(sp + 0, acc.x);
    atomicAdd(sp + 1, acc.y);
    atomicAdd(sp + 2, acc.z);
    atomicAdd(sp + 3, acc.w);
}

__global__ void k_out(float* __restrict__ out) {
    int i = blockIdx.x * blockDim.x + threadIdx.x;
    if (i < GG * DD) out[i] = g_sums[i] / fmaxf(g_cnt[i >> 7], 1.0f);
}

// ---------------- launch (host passes ONLY harness pointers) ----------------
extern "C" void kernel_launch(void* const* d_in, const int* in_sizes, int n_in,
                              void* d_out, int out_size) {
    const float* x = (const float*)d_in[0];
    const int* ei = (const int*)d_in[1];
    const int* batch = (const int*)d_in[2];
    const float* W = (const float*)d_in[3];
    const float* b = (const float*)d_in[4];
    const float* gamma = (const float*)d_in[5];
    const float* beta = (const float*)d_in[6];
    float* out = (float*)d_out;

    const int* src = ei;
    const int* dst = ei + EE;

    int nscan = (NN + SCB - 1) / SCB;  // 49

    cudaFuncSetAttribute(k_gemm_bf16, cudaFuncAttributeMaxDynamicSharedMemorySize, 65536);

    k_initcopy<<<(NN * DD / 4 + 255) / 256, 256>>>(x);
    k_deg<<<(EE + 255) / 256, 256>>>(dst);
    k_cnt<<<(NN + 255) / 256, 256>>>(batch);
    k_wsplit<<<(LL * 4096 + 255) / 256, 256>>>(W);
    k_scan1<<<nscan, SCB>>>();
    k_scan2<<<1, 32>>>(nscan);
    k_scan3<<<nscan + 1, SCB>>>();
    k_fill<<<(EE + 255) / 256, 256>>>(src, dst);

    for (int l = 0; l < LL; l++) {
        k_gemm_bf16<<<(NN + 127) / 128, 256, 65536>>>(l);
        k_agg<<<(NN * 32 + 255) / 256, 256>>>(b + l * DD, gamma + l * DD, beta + l * DD);
    }

    k_pool<<<((NN + CH - 1) / CH * 32 + 255) / 256, 256>>>(batch);
    k_out<<<(GG * DD + 255) / 256, 256>>>(out);
}

// round 13
// speedup vs baseline: 1.6904x; 1.0246x over previous
#include <cuda_runtime.h>
#include <cuda_bf16.h>
#include <cuda_fp16.h>

#define NN 50000
#define EE 600000
#define DD 128
#define LL 4
#define GG 128

// ---------------- scratch (device globals; referenced ONLY in device code) ----------------
static __device__ int    g_degi[NN];
static __device__ float  g_dinv[NN];
static __device__ int    g_off[NN + 1];
static __device__ int    g_cursor[NN];
static __device__ int    g_bsum[64];
static __device__ int    g_esrc[EE];
static __device__ float  g_ecoef[EE];
static __device__ float  g_xc[NN * DD];       // current features (written by agg each layer)
static __device__ __half g_h16[NN * DD];      // x @ W in fp16 (gather payload)
static __device__ uint4  g_wsplit[LL * 4096]; // pre-split bf16 W in fragment layout
static __device__ float  g_sums[GG * DD];
static __device__ float  g_cnt[GG];

// ---------------- init: zero histograms / pool ----------------
__global__ void k_init() {
    int i = blockIdx.x * blockDim.x + threadIdx.x;
    if (i < NN) { g_degi[i] = 0; g_cursor[i] = 0; }
    if (i < GG * DD) g_sums[i] = 0.f;
    if (i < GG) g_cnt[i] = 0.f;
}

// ---------------- helpers ----------------
__device__ __forceinline__ unsigned pack_bf(float lo_f, float hi_f) {
    __nv_bfloat162 p;
    p.x = __float2bfloat16(lo_f);   // .x = low half (even k)
    p.y = __float2bfloat16(hi_f);
    return *(unsigned*)&p;
}

// ---------------- fused preproc: deg histogram + batch histogram + W split ----------------
__global__ void k_pre(const int* __restrict__ dst, const int* __restrict__ batch,
                      const float* __restrict__ W) {
    __shared__ int hist[GG];
    int tid = threadIdx.x;
    int i = blockIdx.x * blockDim.x + tid;

    if (tid < GG) hist[tid] = 0;

    // --- degree histogram over edges ---
    if (i < EE) atomicAdd(&g_degi[dst[i]], 1);

    // --- W split into bf16 hi/lo fragment layout ---
    if (i < LL * 4096) {
        int t = i;
        int l = t >> 12;
        int u = t & 4095;
        int tig = u & 3;
        int nlow = (u >> 2) & 1;
        int kc = (u >> 3) & 7;
        int npair = u >> 6;
        int n = npair * 2 + nlow;
        int k0 = kc * 16 + tig * 2;
        const float* Wl = W + l * DD * DD;
        float w00 = Wl[k0 * DD + n],       w01 = Wl[(k0 + 1) * DD + n];
        float w80 = Wl[(k0 + 8) * DD + n], w81 = Wl[(k0 + 9) * DD + n];
        float h00 = __bfloat162float(__float2bfloat16(w00));
        float h01 = __bfloat162float(__float2bfloat16(w01));
        float h80 = __bfloat162float(__float2bfloat16(w80));
        float h81 = __bfloat162float(__float2bfloat16(w81));
        uint4 v;
        v.x = pack_bf(w00, w01);
        v.y = pack_bf(w80, w81);
        v.z = pack_bf(w00 - h00, w01 - h01);
        v.w = pack_bf(w80 - h80, w81 - h81);
        g_wsplit[t] = v;
    }

    // --- graph-size histogram (block-local then global) ---
    __syncthreads();
    if (i < NN) atomicAdd(&hist[batch[i]], 1);
    __syncthreads();
    if (tid < GG && hist[tid] > 0) atomicAdd(&g_cnt[tid], (float)hist[tid]);
}

// ---------------- exclusive scan of g_degi -> g_off (also computes dinv) ----------------
#define SCB 1024
__global__ void k_scan1() {
    __shared__ int sh[SCB];
    int i = blockIdx.x * SCB + threadIdx.x;
    int v = (i < NN) ? g_degi[i] : 0;
    if (i < NN) g_dinv[i] = rsqrtf((float)v + 1.0f);
    sh[threadIdx.x] = v;
    __syncthreads();
#pragma unroll
    for (int o = 1; o < SCB; o <<= 1) {
        int t = 0;
        if ((int)threadIdx.x >= o) t = sh[threadIdx.x - o];
        __syncthreads();
        if ((int)threadIdx.x >= o) sh[threadIdx.x] += t;
        __syncthreads();
    }
    if (i < NN) g_off[i] = sh[threadIdx.x] - v;
    if (threadIdx.x == SCB - 1) g_bsum[blockIdx.x] = sh[SCB - 1];
}

__global__ void k_scan2(int nblocks) {
    if (threadIdx.x == 0) {
        int run = 0;
        for (int b = 0; b < nblocks; b++) {
            int t = g_bsum[b];
            g_bsum[b] = run;
            run += t;
        }
    }
}

__global__ void k_scan3() {
    int i = blockIdx.x * SCB + threadIdx.x;
    if (i < NN) g_off[i] += g_bsum[blockIdx.x];
    if (i == NN) g_off[NN] = EE;
}

// ---------------- fill CSR ----------------
__global__ void k_fill(const int* __restrict__ src, const int* __restrict__ dst) {
    int e = blockIdx.x * blockDim.x + threadIdx.x;
    if (e >= EE) return;
    int s = src[e], d = dst[e];
    int p = g_off[d] + atomicAdd(&g_cursor[d], 1);
    g_esrc[p] = s;
    g_ecoef[p] = g_dinv[s] * g_dinv[d];
}

// ---------------- tensor-core GEMM: g_h16 = fp16(xin @ W[l]), bf16 split ----------------
#define MMA_BF16(c, a0, a1, a2, a3, b0, b1)                                  \
    asm volatile(                                                            \
        "mma.sync.aligned.m16n8k16.row.col.f32.bf16.bf16.f32 "               \
        "{%0,%1,%2,%3}, {%4,%5,%6,%7}, {%8,%9}, {%0,%1,%2,%3};"              \
        : "+f"(c[0]), "+f"(c[1]), "+f"(c[2]), "+f"(c[3])                     \
        : "r"(a0), "r"(a1), "r"(a2), "r"(a3), "r"(b0), "r"(b1))

__device__ __forceinline__ void split2(float2 f, unsigned& hi, unsigned& lo) {
    float hx = __bfloat162float(__float2bfloat16(f.x));
    float hy = __bfloat162float(__float2bfloat16(f.y));
    hi = pack_bf(f.x, f.y);
    lo = pack_bf(f.x - hx, f.y - hy);
}

__global__ void __launch_bounds__(256) k_gemm_bf16(int l, const float* __restrict__ xe, int ext) {
    extern __shared__ uint4 Bs[];  // 4096 uint4 = 64KB, fragment layout
    int tid = threadIdx.x;
    const uint4* wsrc = g_wsplit + l * 4096;
#pragma unroll
    for (int i = 0; i < 16; i++) Bs[tid + i * 256] = wsrc[tid + i * 256];
    __syncthreads();

    const float* xp = ext ? xe : (const float*)g_xc;

    int warp = tid >> 5, lane = tid & 31;
    int gID = lane >> 2, tig = lane & 3;
    int rA = blockIdx.x * 128 + warp * 16 + gID;
    int rB = rA + 8;
    bool vA = rA < NN, vB = rB < NN;
    int tb = (gID >> 1) * 64 + (gID & 1) * 4 + tig;  // per-thread smem base

    float acc[16][4];
#pragma unroll
    for (int i = 0; i < 16; i++) {
        acc[i][0] = 0.f; acc[i][1] = 0.f; acc[i][2] = 0.f; acc[i][3] = 0.f;
    }

    const float2 z2 = make_float2(0.f, 0.f);
#pragma unroll
    for (int kc = 0; kc < 8; kc++) {
        int kb = kc * 16 + tig * 2;
        float2 fA0 = vA ? *(const float2*)&xp[rA * DD + kb] : z2;
        float2 fA8 = vA ? *(const float2*)&xp[rA * DD + kb + 8] : z2;
        float2 fB0 = vB ? *(const float2*)&xp[rB * DD + kb] : z2;
        float2 fB8 = vB ? *(const float2*)&xp[rB * DD + kb + 8] : z2;
        unsigned ah0, al0, ah1, al1, ah2, al2, ah3, al3;
        split2(fA0, ah0, al0);
        split2(fB0, ah1, al1);
        split2(fA8, ah2, al2);
        split2(fB8, ah3, al3);
#pragma unroll
        for (int nt = 0; nt < 16; nt++) {
            uint4 bv = Bs[nt * 256 + kc * 8 + tb];
            MMA_BF16(acc[nt], ah0, ah1, ah2, ah3, bv.x, bv.y);  // hi*hi
            MMA_BF16(acc[nt], ah0, ah1, ah2, ah3, bv.z, bv.w);  // hi*lo
            MMA_BF16(acc[nt], al0, al1, al2, al3, bv.x, bv.y);  // lo*hi
        }
    }
#pragma unroll
    for (int nt = 0; nt < 16; nt++) {
        int c = nt * 8 + tig * 2;
        if (vA) {
            __half2 p = __floats2half2_rn(acc[nt][0], acc[nt][1]);
            *(__half2*)&g_h16[rA * DD + c] = p;
        }
        if (vB) {
            __half2 p = __floats2half2_rn(acc[nt][2], acc[nt][3]);
            *(__half2*)&g_h16[rB * DD + c] = p;
        }
    }
}

// ---------------- fused: gather-agg + self-loop + residual + bias + LN + ReLU ----------------
__device__ __forceinline__ float4 ld_h4(int s, int c4) {
    uint2 raw = *(const uint2*)&g_h16[s * DD + c4];
    __half2 p0 = *(__half2*)&raw.x;
    __half2 p1 = *(__half2*)&raw.y;
    float2 f0 = __half22float2(p0);
    float2 f1 = __half22float2(p1);
    return make_float4(f0.x, f0.y, f1.x, f1.y);
}

__global__ void k_agg(const float* __restrict__ bl,
                      const float* __restrict__ gl,
                      const float* __restrict__ betal,
                      const float* __restrict__ xe, int ext) {
    int warp = (blockIdx.x * blockDim.x + threadIdx.x) >> 5;
    if (warp >= NN) return;
    int lane = threadIdx.x & 31;
    int n = warp;
    int c4 = lane * 4;

    float4 acc = make_float4(0.f, 0.f, 0.f, 0.f);
    int j = g_off[n];
    int jend = g_off[n + 1];
    for (; j + 3 < jend; j += 4) {
        int s0 = g_esrc[j],     s1 = g_esrc[j + 1];
        int s2 = g_esrc[j + 2], s3 = g_esrc[j + 3];
        float c0 = g_ecoef[j],     c1 = g_ecoef[j + 1];
        float c2 = g_ecoef[j + 2], c3 = g_ecoef[j + 3];
        float4 h0 = ld_h4(s0, c4);
        float4 h1 = ld_h4(s1, c4);
        float4 h2 = ld_h4(s2, c4);
        float4 h3 = ld_h4(s3, c4);
        acc.x += h0.x * c0 + h1.x * c1 + h2.x * c2 + h3.x * c3;
        acc.y += h0.y * c0 + h1.y * c1 + h2.y * c2 + h3.y * c3;
        acc.z += h0.z * c0 + h1.z * c1 + h2.z * c2 + h3.z * c3;
        acc.w += h0.w * c0 + h1.w * c1 + h2.w * c2 + h3.w * c3;
    }
    for (; j < jend; j++) {
        int s0 = g_esrc[j];
        float c0 = g_ecoef[j];
        float4 h0 = ld_h4(s0, c4);
        acc.x += h0.x * c0;
        acc.y += h0.y * c0;
        acc.z += h0.z * c0;
        acc.w += h0.w * c0;
    }

    const float* xp = ext ? xe : (const float*)g_xc;
    float di = g_dinv[n];
    float self = di * di;
    int base = n * DD + c4;
    float4 xv = *(const float4*)&xp[base];
    float4 hv = ld_h4(n, c4);
    float4 bv = *(const float4*)&bl[c4];

    float v0 = xv.x + acc.x + hv.x * self + bv.x;
    float v1 = xv.y + acc.y + hv.y * self + bv.y;
    float v2 = xv.z + acc.z + hv.z * self + bv.z;
    float v3 = xv.w + acc.w + hv.w * self + bv.w;

    float s = v0 + v1 + v2 + v3;
#pragma unroll
    for (int o = 16; o > 0; o >>= 1) s += __shfl_xor_sync(0xffffffffu, s, o);
    float m = s * (1.0f / DD);

    float d0 = v0 - m, d1 = v1 - m, d2 = v2 - m, d3 = v3 - m;
    float sq = d0 * d0 + d1 * d1 + d2 * d2 + d3 * d3;
#pragma unroll
    for (int o = 16; o > 0; o >>= 1) sq += __shfl_xor_sync(0xffffffffu, sq, o);
    float inv = rsqrtf(sq * (1.0f / DD) + 1e-5f);

    float4 gv = *(const float4*)&gl[c4];
    float4 tv = *(const float4*)&betal[c4];
    float4 outv;
    outv.x = fmaxf(d0 * inv * gv.x + tv.x, 0.f);
    outv.y = fmaxf(d1 * inv * gv.y + tv.y, 0.f);
    outv.z = fmaxf(d2 * inv * gv.z + tv.z, 0.f);
    outv.w = fmaxf(d3 * inv * gv.w + tv.w, 0.f);
    *(float4*)&g_xc[base] = outv;
}

// ---------------- global mean pool: warp-chunked accumulation ----------------
#define CH 16
__global__ void k_pool(const int* __restrict__ batch) {
    int warp = (blockIdx.x * blockDim.x + threadIdx.x) >> 5;
    int lane = threadIdx.x & 31;
    int n0 = warp * CH;
    if (n0 >= NN) return;
    int n1 = n0 + CH;
    if (n1 > NN) n1 = NN;

    float4 acc = make_float4(0.f, 0.f, 0.f, 0.f);
    int cur = batch[n0];
    for (int n = n0; n < n1; n++) {
        int g = batch[n];
        if (g != cur) {
            float* sp = &g_sums[cur * DD + lane * 4];
            atomicAdd(sp + 0, acc.x);
            atomicAdd(sp + 1, acc.y);
            atomicAdd(sp + 2, acc.z);
            atomicAdd(sp + 3, acc.w);
            acc = make_float4(0.f, 0.f, 0.f, 0.f);
            cur = g;
        }
        float4 xv = *(const float4*)&g_xc[n * DD + lane * 4];
        acc.x += xv.x; acc.y += xv.y; acc.z += xv.z; acc.w += xv.w;
    }
    float* sp = &g_sums[cur * DD + lane * 4];
    atomicAdd(sp + 0, acc.x);
    atomicAdd(sp + 1, acc.y);
    atomicAdd(sp + 2, acc.z);
    atomicAdd(sp + 3, acc.w);
}

__global__ void k_out(float* __restrict__ out) {
    int i = blockIdx.x * blockDim.x + threadIdx.x;
    if (i < GG * DD) out[i] = g_sums[i] / fmaxf(g_cnt[i >> 7], 1.0f);
}

// ---------------- launch (host passes ONLY harness pointers) ----------------
extern "C" void kernel_launch(void* const* d_in, const int* in_sizes, int n_in,
                              void* d_out, int out_size) {
    const float* x = (const float*)d_in[0];
    const int* ei = (const int*)d_in[1];
    const int* batch = (const int*)d_in[2];
    const float* W = (const float*)d_in[3];
    const float* b = (const float*)d_in[4];
    const float* gamma = (const float*)d_in[5];
    const float* beta = (const float*)d_in[6];
    float* out = (float*)d_out;

    const int* src = ei;
    const int* dst = ei + EE;

    int nscan = (NN + SCB - 1) / SCB;  // 49

    cudaFuncSetAttribute(k_gemm_bf16, cudaFuncAttributeMaxDynamicSharedMemorySize, 65536);

    k_init<<<(NN + 255) / 256, 256>>>();
    k_pre<<<(EE + 255) / 256, 256>>>(dst, batch, W);
    k_scan1<<<nscan, SCB>>>();
    k_scan2<<<1, 32>>>(nscan);
    k_scan3<<<nscan + 1, SCB>>>();
    k_fill<<<(EE + 255) / 256, 256>>>(src, dst);

    for (int l = 0; l < LL; l++) {
        int ext = (l == 0) ? 1 : 0;
        k_gemm_bf16<<<(NN + 127) / 128, 256, 65536>>>(l, x, ext);
        k_agg<<<(NN * 32 + 255) / 256, 256>>>(b + l * DD, gamma + l * DD, beta + l * DD, x, ext);
    }

    k_pool<<<((NN + CH - 1) / CH * 32 + 255) / 256, 256>>>(batch);
    k_out<<<(GG * DD + 255) / 256, 256>>>(out);
}

// round 14
// speedup vs baseline: 1.7098x; 1.0115x over previous
#include <cuda_runtime.h>
#include <cuda_bf16.h>
#include <cuda_fp16.h>

#define NN 50000
#define EE 600000
#define DD 128
#define LL 4
#define GG 128

// ---------------- scratch (device globals; referenced ONLY in device code) ----------------
static __device__ int    g_degi[NN];
static __device__ float  g_dinv[NN];
static __device__ int    g_off[NN + 1];
static __device__ int    g_cursor[NN];
static __device__ int    g_bsum[64];
static __device__ int    g_esrc[EE];
static __device__ float  g_ecoef[EE];
static __device__ __half g_xc[NN * DD];       // current features, fp16 (in-place per layer)
static __device__ __half g_h16[NN * DD];      // x @ W in fp16 (gather payload)
static __device__ uint4  g_wsplit[LL * 4096]; // pre-split bf16 W in fragment layout
static __device__ float  g_sums[GG * DD];
static __device__ float  g_cnt[GG];

// ---------------- init: zero histograms / pool + convert x -> fp16 xc ----------------
__global__ void k_init(const float* __restrict__ x) {
    int i = blockIdx.x * blockDim.x + threadIdx.x;
    if (i < NN * DD / 4) {
        float4 v = ((const float4*)x)[i];
        __half2 p0 = __floats2half2_rn(v.x, v.y);
        __half2 p1 = __floats2half2_rn(v.z, v.w);
        uint2 u;
        u.x = *(unsigned*)&p0;
        u.y = *(unsigned*)&p1;
        ((uint2*)g_xc)[i] = u;
    }
    if (i < NN) { g_degi[i] = 0; g_cursor[i] = 0; }
    if (i < GG * DD) g_sums[i] = 0.f;
    if (i < GG) g_cnt[i] = 0.f;
}

// ---------------- helpers ----------------
__device__ __forceinline__ unsigned pack_bf(float lo_f, float hi_f) {
    __nv_bfloat162 p;
    p.x = __float2bfloat16(lo_f);   // .x = low half (even k)
    p.y = __float2bfloat16(hi_f);
    return *(unsigned*)&p;
}

__device__ __forceinline__ float4 ld_half4p(const __half* p) {
    uint2 raw = *(const uint2*)p;
    __half2 p0 = *(__half2*)&raw.x;
    __half2 p1 = *(__half2*)&raw.y;
    float2 f0 = __half22float2(p0);
    float2 f1 = __half22float2(p1);
    return make_float4(f0.x, f0.y, f1.x, f1.y);
}

// ---------------- fused preproc: deg histogram + batch histogram + W split ----------------
__global__ void k_pre(const int* __restrict__ dst, const int* __restrict__ batch,
                      const float* __restrict__ W) {
    __shared__ int hist[GG];
    int tid = threadIdx.x;
    int i = blockIdx.x * blockDim.x + tid;

    if (tid < GG) hist[tid] = 0;

    if (i < EE) atomicAdd(&g_degi[dst[i]], 1);

    if (i < LL * 4096) {
        int t = i;
        int l = t >> 12;
        int u = t & 4095;
        int tig = u & 3;
        int nlow = (u >> 2) & 1;
        int kc = (u >> 3) & 7;
        int npair = u >> 6;
        int n = npair * 2 + nlow;
        int k0 = kc * 16 + tig * 2;
        const float* Wl = W + l * DD * DD;
        float w00 = Wl[k0 * DD + n],       w01 = Wl[(k0 + 1) * DD + n];
        float w80 = Wl[(k0 + 8) * DD + n], w81 = Wl[(k0 + 9) * DD + n];
        float h00 = __bfloat162float(__float2bfloat16(w00));
        float h01 = __bfloat162float(__float2bfloat16(w01));
        float h80 = __bfloat162float(__float2bfloat16(w80));
        float h81 = __bfloat162float(__float2bfloat16(w81));
        uint4 v;
        v.x = pack_bf(w00, w01);
        v.y = pack_bf(w80, w81);
        v.z = pack_bf(w00 - h00, w01 - h01);
        v.w = pack_bf(w80 - h80, w81 - h81);
        g_wsplit[t] = v;
    }

    __syncthreads();
    if (i < NN) atomicAdd(&hist[batch[i]], 1);
    __syncthreads();
    if (tid < GG && hist[tid] > 0) atomicAdd(&g_cnt[tid], (float)hist[tid]);
}

// ---------------- exclusive scan of g_degi -> g_off (also computes dinv) ----------------
#define SCB 1024
__global__ void k_scan1() {
    __shared__ int sh[SCB];
    int i = blockIdx.x * SCB + threadIdx.x;
    int v = (i < NN) ? g_degi[i] : 0;
    if (i < NN) g_dinv[i] = rsqrtf((float)v + 1.0f);
    sh[threadIdx.x] = v;
    __syncthreads();
#pragma unroll
    for (int o = 1; o < SCB; o <<= 1) {
        int t = 0;
        if ((int)threadIdx.x >= o) t = sh[threadIdx.x - o];
        __syncthreads();
        if ((int)threadIdx.x >= o) sh[threadIdx.x] += t;
        __syncthreads();
    }
    if (i < NN) g_off[i] = sh[threadIdx.x] - v;
    if (threadIdx.x == SCB - 1) g_bsum[blockIdx.x] = sh[SCB - 1];
}

// scan3 now also does the block-prefix of g_bsum itself (replaces serial k_scan2)
__global__ void k_scan3() {
    __shared__ int pre_sh;
    int tid = threadIdx.x;
    if (tid < 32) {
        int acc = 0;
        for (int b = tid; b < (int)blockIdx.x; b += 32) acc += g_bsum[b];
#pragma unroll
        for (int o = 16; o > 0; o >>= 1) acc += __shfl_xor_sync(0xffffffffu, acc, o);
        if (tid == 0) pre_sh = acc;
    }
    __syncthreads();
    int i = blockIdx.x * SCB + tid;
    if (i < NN) g_off[i] += pre_sh;
    if (i == NN) g_off[NN] = EE;
}

// ---------------- fill CSR ----------------
__global__ void k_fill(const int* __restrict__ src, const int* __restrict__ dst) {
    int e = blockIdx.x * blockDim.x + threadIdx.x;
    if (e >= EE) return;
    int s = src[e], d = dst[e];
    int p = g_off[d] + atomicAdd(&g_cursor[d], 1);
    g_esrc[p] = s;
    g_ecoef[p] = g_dinv[s] * g_dinv[d];
}

// ---------------- tensor-core GEMM: g_h16 = fp16(g_xc @ W[l]), bf16 split ----------------
#define MMA_BF16(c, a0, a1, a2, a3, b0, b1)                                  \
    asm volatile(                                                            \
        "mma.sync.aligned.m16n8k16.row.col.f32.bf16.bf16.f32 "               \
        "{%0,%1,%2,%3}, {%4,%5,%6,%7}, {%8,%9}, {%0,%1,%2,%3};"              \
        : "+f"(c[0]), "+f"(c[1]), "+f"(c[2]), "+f"(c[3])                     \
        : "r"(a0), "r"(a1), "r"(a2), "r"(a3), "r"(b0), "r"(b1))

// fp16 -> (bf16 hi, bf16 lo): exact (11 mantissa bits <= 8+8)
__device__ __forceinline__ void split_h2(__half2 h, unsigned& hi, unsigned& lo) {
    float2 f = __half22float2(h);
    float hx = __bfloat162float(__float2bfloat16(f.x));
    float hy = __bfloat162float(__float2bfloat16(f.y));
    hi = pack_bf(f.x, f.y);
    lo = pack_bf(f.x - hx, f.y - hy);
}

__global__ void __launch_bounds__(256) k_gemm_bf16(int l) {
    extern __shared__ uint4 Bs[];  // 4096 uint4 = 64KB, fragment layout
    int tid = threadIdx.x;
    const uint4* wsrc = g_wsplit + l * 4096;
#pragma unroll
    for (int i = 0; i < 16; i++) Bs[tid + i * 256] = wsrc[tid + i * 256];
    __syncthreads();

    int warp = tid >> 5, lane = tid & 31;
    int gID = lane >> 2, tig = lane & 3;
    int rA = blockIdx.x * 128 + warp * 16 + gID;
    int rB = rA + 8;
    bool vA = rA < NN, vB = rB < NN;
    int tb = (gID >> 1) * 64 + (gID & 1) * 4 + tig;  // per-thread smem base

    float acc[16][4];
#pragma unroll
    for (int i = 0; i < 16; i++) {
        acc[i][0] = 0.f; acc[i][1] = 0.f; acc[i][2] = 0.f; acc[i][3] = 0.f;
    }

    const __half2 z2h = __floats2half2_rn(0.f, 0.f);
#pragma unroll
    for (int kc = 0; kc < 8; kc++) {
        int kb = kc * 16 + tig * 2;
        __half2 fA0 = vA ? *(const __half2*)&g_xc[rA * DD + kb] : z2h;
        __half2 fA8 = vA ? *(const __half2*)&g_xc[rA * DD + kb + 8] : z2h;
        __half2 fB0 = vB ? *(const __half2*)&g_xc[rB * DD + kb] : z2h;
        __half2 fB8 = vB ? *(const __half2*)&g_xc[rB * DD + kb + 8] : z2h;
        unsigned ah0, al0, ah1, al1, ah2, al2, ah3, al3;
        split_h2(fA0, ah0, al0);
        split_h2(fB0, ah1, al1);
        split_h2(fA8, ah2, al2);
        split_h2(fB8, ah3, al3);
#pragma unroll
        for (int nt = 0; nt < 16; nt++) {
            uint4 bv = Bs[nt * 256 + kc * 8 + tb];
            MMA_BF16(acc[nt], ah0, ah1, ah2, ah3, bv.x, bv.y);  // hi*hi
            MMA_BF16(acc[nt], ah0, ah1, ah2, ah3, bv.z, bv.w);  // hi*lo
            MMA_BF16(acc[nt], al0, al1, al2, al3, bv.x, bv.y);  // lo*hi
        }
    }
#pragma unroll
    for (int nt = 0; nt < 16; nt++) {
        int c = nt * 8 + tig * 2;
        if (vA) {
            __half2 p = __floats2half2_rn(acc[nt][0], acc[nt][1]);
            *(__half2*)&g_h16[rA * DD + c] = p;
        }
        if (vB) {
            __half2 p = __floats2half2_rn(acc[nt][2], acc[nt][3]);
            *(__half2*)&g_h16[rB * DD + c] = p;
        }
    }
}

// ---------------- fused: gather-agg + self-loop + residual + bias + LN + ReLU ----------------
__global__ void k_agg(const float* __restrict__ bl,
                      const float* __restrict__ gl,
                      const float* __restrict__ betal) {
    int warp = (blockIdx.x * blockDim.x + threadIdx.x) >> 5;
    if (warp >= NN) return;
    int lane = threadIdx.x & 31;
    int n = warp;
    int c4 = lane * 4;

    float4 acc = make_float4(0.f, 0.f, 0.f, 0.f);
    int j = g_off[n];
    int jend = g_off[n + 1];
    for (; j + 3 < jend; j += 4) {
        int s0 = g_esrc[j],     s1 = g_esrc[j + 1];
        int s2 = g_esrc[j + 2], s3 = g_esrc[j + 3];
        float c0 = g_ecoef[j],     c1 = g_ecoef[j + 1];
        float c2 = g_ecoef[j + 2], c3 = g_ecoef[j + 3];
        float4 h0 = ld_half4p(g_h16 + s0 * DD + c4);
        float4 h1 = ld_half4p(g_h16 + s1 * DD + c4);
        float4 h2 = ld_half4p(g_h16 + s2 * DD + c4);
        float4 h3 = ld_half4p(g_h16 + s3 * DD + c4);
        acc.x += h0.x * c0 + h1.x * c1 + h2.x * c2 + h3.x * c3;
        acc.y += h0.y * c0 + h1.y * c1 + h2.y * c2 + h3.y * c3;
        acc.z += h0.z * c0 + h1.z * c1 + h2.z * c2 + h3.z * c3;
        acc.w += h0.w * c0 + h1.w * c1 + h2.w * c2 + h3.w * c3;
    }
    for (; j < jend; j++) {
        int s0 = g_esrc[j];
        float c0 = g_ecoef[j];
        float4 h0 = ld_half4p(g_h16 + s0 * DD + c4);
        acc.x += h0.x * c0;
        acc.y += h0.y * c0;
        acc.z += h0.z * c0;
        acc.w += h0.w * c0;
    }

    float di = g_dinv[n];
    float self = di * di;
    int base = n * DD + c4;
    float4 xv = ld_half4p(g_xc + base);
    float4 hv = ld_half4p(g_h16 + base);
    float4 bv = *(const float4*)&bl[c4];

    float v0 = xv.x + acc.x + hv.x * self + bv.x;
    float v1 = xv.y + acc.y + hv.y * self + bv.y;
    float v2 = xv.z + acc.z + hv.z * self + bv.z;
    float v3 = xv.w + acc.w + hv.w * self + bv.w;

    float s = v0 + v1 + v2 + v3;
#pragma unroll
    for (int o = 16; o > 0; o >>= 1) s += __shfl_xor_sync(0xffffffffu, s, o);
    float m = s * (1.0f / DD);

    float d0 = v0 - m, d1 = v1 - m, d2 = v2 - m, d3 = v3 - m;
    float sq = d0 * d0 + d1 * d1 + d2 * d2 + d3 * d3;
#pragma unroll
    for (int o = 16; o > 0; o >>= 1) sq += __shfl_xor_sync(0xffffffffu, sq, o);
    float inv = rsqrtf(sq * (1.0f / DD) + 1e-5f);

    float4 gv = *(const float4*)&gl[c4];
    float4 tv = *(const float4*)&betal[c4];
    float o0 = fmaxf(d0 * inv * gv.x + tv.x, 0.f);
    float o1 = fmaxf(d1 * inv * gv.y + tv.y, 0.f);
    float o2 = fmaxf(d2 * inv * gv.z + tv.z, 0.f);
    float o3 = fmaxf(d3 * inv * gv.w + tv.w, 0.f);

    __half2 p0 = __floats2half2_rn(o0, o1);
    __half2 p1 = __floats2half2_rn(o2, o3);
    uint2 u;
    u.x = *(unsigned*)&p0;
    u.y = *(unsigned*)&p1;
    *(uint2*)&g_xc[base] = u;
}

// ---------------- global mean pool: warp-chunked accumulation ----------------
#define CH 16
__global__ void k_pool(const int* __restrict__ batch) {
    int warp = (blockIdx.x * blockDim.x + threadIdx.x) >> 5;
    int lane = threadIdx.x & 31;
    int n0 = warp * CH;
    if (n0 >= NN) return;
    int n1 = n0 + CH;
    if (n1 > NN) n1 = NN;

    float4 acc = make_float4(0.f, 0.f, 0.f, 0.f);
    int cur = batch[n0];
    for (int n = n0; n < n1; n++) {
        int g = batch[n];
        if (g != cur) {
            float* sp = &g_sums[cur * DD + lane * 4];
            atomicAdd(sp + 0, acc.x);
            atomicAdd(sp + 1, acc.y);
            atomicAdd(sp + 2, acc.z);
            atomicAdd(sp + 3, acc.w);
            acc = make_float4(0.f, 0.f, 0.f, 0.f);
            cur = g;
        }
        float4 xv = ld_half4p(g_xc + n * DD + lane * 4);
        acc.x += xv.x; acc.y += xv.y; acc.z += xv.z; acc.w += xv.w;
    }
    float* sp = &g_sums[cur * DD + lane * 4];
    atomicAdd(sp + 0, acc.x);
    atomicAdd(sp + 1, acc.y);
    atomicAdd(sp + 2, acc.z);
    atomicAdd(sp + 3, acc.w);
}

__global__ void k_out(float* __restrict__ out) {
    int i = blockIdx.x * blockDim.x + threadIdx.x;
    if (i < GG * DD) out[i] = g_sums[i] / fmaxf(g_cnt[i >> 7], 1.0f);
}

// ---------------- launch (host passes ONLY harness pointers) ----------------
extern "C" void kernel_launch(void* const* d_in, const int* in_sizes, int n_in,
                              void* d_out, int out_size) {
    const float* x = (const float*)d_in[0];
    const int* ei = (const int*)d_in[1];
    const int* batch = (const int*)d_in[2];
    const float* W = (const float*)d_in[3];
    const float* b = (const float*)d_in[4];
    const float* gamma = (const float*)d_in[5];
    const float* beta = (const float*)d_in[6];
    float* out = (float*)d_out;

    const int* src = ei;
    const int* dst = ei + EE;

    int nscan = (NN + SCB - 1) / SCB;  // 49

    cudaFuncSetAttribute(k_gemm_bf16, cudaFuncAttributeMaxDynamicSharedMemorySize, 65536);

    k_init<<<(NN * DD / 4 + 255) / 256, 256>>>(x);
    k_pre<<<(EE + 255) / 256, 256>>>(dst, batch, W);
    k_scan1<<<nscan, SCB>>>();
    k_scan3<<<nscan, SCB>>>();
    k_fill<<<(EE + 255) / 256, 256>>>(src, dst);

    for (int l = 0; l < LL; l++) {
        k_gemm_bf16<<<(NN + 127) / 128, 256, 65536>>>(l);
        k_agg<<<(NN * 32 + 255) / 256, 256>>>(b + l * DD, gamma + l * DD, beta + l * DD);
    }

    k_pool<<<((NN + CH - 1) / CH * 32 + 255) / 256, 256>>>(batch);
    k_out<<<(GG * DD + 255) / 256, 256>>>(out);
}